// round 14
// baseline (speedup 1.0000x reference)
#include <cuda_runtime.h>
#include <cuda_bf16.h>
#include <cstdint>

#define EMB   768
#define HEADS 8
#define HDIM  96
#define BATCH 4
#define SEQ   2048
#define ROWS  (BATCH*SEQ)      /* 8192 */
#define QKV_N (3*EMB)          /* 2304 */
#define INV_SCALE 0.10206207261596577f   /* 1/sqrt(96) */

typedef unsigned long long ull;

// ---------------- scratch (static device globals: allocation-free) ----------
__device__ float g_q[BATCH*HEADS*HDIM*SEQ];   // [bh][d][n]
__device__ float g_k[BATCH*HEADS*HDIM*SEQ];   // [bh][d][n]
__device__ float g_v[BATCH*HEADS*SEQ*HDIM];   // [bh][n][d]
__device__ float g_attn[ROWS*EMB];

// ---------------- f32x2 helpers (packed fp32, for flash) --------------------
__device__ __forceinline__ ull pack2(float lo, float hi){
    ull r; asm("mov.b64 %0, {%1, %2};" : "=l"(r) : "f"(lo), "f"(hi)); return r;
}
__device__ __forceinline__ void unpack2(ull v, float& lo, float& hi){
    asm("mov.b64 {%0, %1}, %2;" : "=f"(lo), "=f"(hi) : "l"(v));
}
__device__ __forceinline__ ull fma2(ull a, ull b, ull c){
    ull d; asm("fma.rn.f32x2 %0, %1, %2, %3;" : "=l"(d) : "l"(a), "l"(b), "l"(c)); return d;
}
__device__ __forceinline__ ull mul2(ull a, ull b){
    ull d; asm("mul.rn.f32x2 %0, %1, %2;" : "=l"(d) : "l"(a), "l"(b)); return d;
}

// ---------------- mma.sync helpers (Ampere-era PTX, valid on compute_103) ---
__device__ __forceinline__ uint32_t smem_u32(const void* p){
    uint32_t a;
    asm("{ .reg .u64 t; cvta.to.shared.u64 t, %1; cvt.u32.u64 %0, t; }" : "=r"(a) : "l"(p));
    return a;
}
#define LDM4(r, addr) \
    asm volatile("ldmatrix.sync.aligned.m8n8.x4.shared.b16 {%0,%1,%2,%3}, [%4];" \
        : "=r"((r)[0]), "=r"((r)[1]), "=r"((r)[2]), "=r"((r)[3]) : "r"(addr))

__device__ __forceinline__ void mma_bf16(float* c, const uint32_t* a, const uint32_t* b){
    asm volatile("mma.sync.aligned.m16n8k16.row.col.f32.bf16.bf16.f32 "
        "{%0,%1,%2,%3}, {%4,%5,%6,%7}, {%8,%9}, {%0,%1,%2,%3};"
        : "+f"(c[0]), "+f"(c[1]), "+f"(c[2]), "+f"(c[3])
        : "r"(a[0]), "r"(a[1]), "r"(a[2]), "r"(a[3]), "r"(b[0]), "r"(b[1]));
}

// split fp32 pair -> packed bf16x2 hi and lo  (bf16x3 decomposition)
__device__ __forceinline__ void split2(float a, float b, uint32_t& hi, uint32_t& lo){
    __nv_bfloat162 h = __floats2bfloat162_rn(a, b);
    float ra = a - __bfloat162float(h.x);
    float rb = b - __bfloat162float(h.y);
    __nv_bfloat162 l = __floats2bfloat162_rn(ra, rb);
    hi = *reinterpret_cast<uint32_t*>(&h);
    lo = *reinterpret_cast<uint32_t*>(&l);
}

// ============================================================================
// mma.sync split-bf16 GEMM: C[M x NC] = A[M x 768] * B[768 x NC] + bias
//   MODE 0: A = x, scatter into g_q/g_k (d-major) and g_v (n-major)
//   MODE 1: A = g_attn, dense write to C (= d_out)
// CTA tile 128x128, BK=64, 256 threads (8 warps: 4 in M x 2 in N;
// warp tile 32m x 64n = 2 m-frags x 8 n-frags of m16n8k16).
// SMEM: k-major rows of 64 bf16 (128B = 8x16B units), unit-XOR swizzle by
// (row&7) -> conflict-free for staging STS and ldmatrix.
// Per k16 step: 12 ldmatrix.x4, 48 HMMA (hi*hi + hi*lo + lo*hi).
// ============================================================================
#define SG_SMEM (64*1024 + 512)
template<int NC, int MODE>
__global__ void __launch_bounds__(256)
gemm_mma(const float* __restrict__ A, const float* __restrict__ B,
         const float* __restrict__ bias, float* __restrict__ C)
{
    extern __shared__ __align__(16) char smraw[];
    char* Ah = smraw;                 // 128 rows x 128B
    char* Al = smraw + 16384;
    char* Bh = smraw + 32768;         // 128 n-rows x 128B
    char* Bl = smraw + 49152;
    float* bs = (float*)(smraw + 65536);

    const uint32_t sb  = smem_u32(smraw);
    const uint32_t AhU = sb, AlU = sb + 16384u, BhU = sb + 32768u, BlU = sb + 49152u;

    const int tid  = threadIdx.x;
    const int wid  = tid >> 5;
    const int lane = tid & 31;
    const int wm   = wid & 3;         // warp row group (32 rows)
    const int wn   = wid >> 2;        // warp col group (64 cols)
    const int bx = blockIdx.x, by = blockIdx.y;

    const float* Asrc = (MODE == 0) ? A : (const float*)g_attn;
    const float* Ag = Asrc + (size_t)by*128*EMB;
    const float* Wg = B + bx*128;

    if (tid < 128) bs[tid] = bias[bx*128 + tid];

    float acc[2][8][4];
    #pragma unroll
    for (int i = 0; i < 2; ++i)
        #pragma unroll
        for (int j = 0; j < 8; ++j)
            #pragma unroll
            for (int e = 0; e < 4; ++e) acc[i][j][e] = 0.f;

    for (int c = 0; c < 12; ++c){
        const int c0 = c*64;
        __syncthreads();   // prev compute done reading smem (and bias STS order)

        // ---- stage A chunk: A[m][c0..c0+63] -> Ah/Al [m][k], swizzled ----
        #pragma unroll
        for (int it = 0; it < 8; ++it){
            int f = tid + it*256;             // 0..2047
            int m = f >> 4, kq = f & 15;      // kq: float4 index (k = 4kq)
            float4 v = *(const float4*)&Ag[(size_t)m*EMB + c0 + 4*kq];
            uint32_t h0, l0, h1, l1;
            split2(v.x, v.y, h0, l0);
            split2(v.z, v.w, h1, l1);
            int u   = kq >> 1;                // 16B unit
            int off = m*128 + (((u ^ (m & 7)))*16) + (kq & 1)*8;
            *(uint2*)(Ah + off) = make_uint2(h0, h1);
            *(uint2*)(Al + off) = make_uint2(l0, l1);
        }
        // ---- stage B chunk (transposed): w[c0+k][n] -> Bh/Bl [n][k], swizzled
        #pragma unroll
        for (int it = 0; it < 4; ++it){
            int t  = tid + it*256;            // 0..1023
            int kp = t >> 5, nq = t & 31;     // k = 2kp, n quad = 4nq
            const float* w0 = Wg + (size_t)(c0 + 2*kp)*NC + 4*nq;
            float4 f0 = *(const float4*)w0;
            float4 f1 = *(const float4*)(w0 + NC);
            const float* p0 = (const float*)&f0;
            const float* p1 = (const float*)&f1;
            #pragma unroll
            for (int e = 0; e < 4; ++e){
                uint32_t h, l;
                split2(p0[e], p1[e], h, l);   // packs (k, k+1) for this n
                int n = 4*nq + e;
                int k = 2*kp;
                int u = k >> 3;
                int off = n*128 + ((u ^ (n & 7))*16) + (k & 7)*2;
                *(uint32_t*)(Bh + off) = h;
                *(uint32_t*)(Bl + off) = l;
            }
        }
        __syncthreads();

        // ---- compute: 4 k16 steps ----
        #pragma unroll
        for (int ks = 0; ks < 4; ++ks){
            uint32_t a_h[2][4], a_l[2][4], b_h[8][2], b_l[8][2];
            #pragma unroll
            for (int fi = 0; fi < 2; ++fi){
                int row = wm*32 + fi*16 + (lane & 15);
                uint32_t byte = (uint32_t)row*128u +
                                (uint32_t)(((ks*2 + (lane >> 4)) ^ (row & 7))*16);
                LDM4(a_h[fi], AhU + byte);
                LDM4(a_l[fi], AlU + byte);
            }
            #pragma unroll
            for (int fp = 0; fp < 4; ++fp){
                int n = wn*64 + fp*16 + (lane & 15);
                uint32_t byte = (uint32_t)n*128u +
                                (uint32_t)(((ks*2 + (lane >> 4)) ^ (n & 7))*16);
                uint32_t th[4], tl[4];
                LDM4(th, BhU + byte);
                LDM4(tl, BlU + byte);
                b_h[2*fp][0]   = th[0]; b_h[2*fp][1]   = th[2];
                b_h[2*fp+1][0] = th[1]; b_h[2*fp+1][1] = th[3];
                b_l[2*fp][0]   = tl[0]; b_l[2*fp][1]   = tl[2];
                b_l[2*fp+1][0] = tl[1]; b_l[2*fp+1][1] = tl[3];
            }
            #pragma unroll
            for (int fi = 0; fi < 2; ++fi)
                #pragma unroll
                for (int fj = 0; fj < 8; ++fj){
                    mma_bf16(acc[fi][fj], a_h[fi], b_h[fj]);
                    mma_bf16(acc[fi][fj], a_h[fi], b_l[fj]);
                    mma_bf16(acc[fi][fj], a_l[fi], b_h[fj]);
                }
        }
    }

    // ---- epilogue ----
    const int lq = lane >> 2, lr = lane & 3;
    #pragma unroll
    for (int fi = 0; fi < 2; ++fi){
        #pragma unroll
        for (int fj = 0; fj < 8; ++fj){
            const float* cc = acc[fi][fj];
            const int lcol = wn*64 + fj*8 + lr*2;
            const int col0 = bx*128 + lcol;
            const int r0   = by*128 + wm*32 + fi*16 + lq;
            if (MODE == 1){
                float2 v0 = make_float2(cc[0] + bs[lcol], cc[1] + bs[lcol+1]);
                float2 v1 = make_float2(cc[2] + bs[lcol], cc[3] + bs[lcol+1]);
                *(float2*)&C[(size_t)r0*NC + col0]     = v0;
                *(float2*)&C[(size_t)(r0+8)*NC + col0] = v1;
            } else {
                #pragma unroll
                for (int h2 = 0; h2 < 2; ++h2){
                    const int m = r0 + 8*h2;
                    const int b = m >> 11, n = m & 2047;
                    #pragma unroll
                    for (int e = 0; e < 2; ++e){
                        const int ccol = col0 + e;
                        const float val = cc[2*h2 + e] + bs[lcol + e];
                        // qkv reshape (B,N,H,D,3): ccol = h*288 + d*3 + which
                        const int which = ccol % 3;
                        const int tt    = ccol / 3;
                        const int d     = tt % HDIM;
                        const int h     = tt / HDIM;
                        const int bh    = b*HEADS + h;
                        if (which == 2)
                            g_v[((size_t)bh*SEQ + n)*HDIM + d] = val;      // [bh][n][d]
                        else
                            ((which == 0) ? g_q : g_k)
                                [((size_t)bh*HDIM + d)*SEQ + n] = val;     // [bh][d][n]
                    }
                }
            }
        }
    }
}

// ============================================================================
// Flash attention (best measured config): fp32 online softmax, 256 threads,
// one block = (bh, 128-query tile), 8x8 micro-tile, f32x2 FMAs.
// softmax(S) applied, 1/sqrt(D) AFTER (faithful to reference).
// ============================================================================
__global__ void __launch_bounds__(256, 1) flash_kernel()
{
    extern __shared__ __align__(16) float smf[];
    float* Qs = smf;                 // [96][128]  k-major
    float* Ks = Qs + 96*128;         // [96][128]  k-major
    float* Vs = Ks + 96*128;         // [128][96]  n-major
    float* Ps = Vs + 128*96;         // [128][128] row-major

    const int tx = threadIdx.x, ty = threadIdx.y;
    const int tid = ty*16 + tx;
    const int n0 = blockIdx.x * 128;
    const int bh = blockIdx.y;

    const float* Qg = g_q + (size_t)bh*HDIM*SEQ;
    const float* Kg = g_k + (size_t)bh*HDIM*SEQ;
    const float* Vg = g_v + (size_t)bh*SEQ*HDIM;

    int row8[8];
    #pragma unroll
    for (int i = 0; i < 8; ++i) row8[i] = (i < 4) ? (4*ty + i) : (64 + 4*ty + i - 4);

    #pragma unroll
    for (int it = 0; it < 12; ++it){
        int f  = tid + it*256;
        int d  = f >> 5;
        int n4 = (f & 31) << 2;
        *(float4*)&Qs[d*128 + n4] = *(const float4*)&Qg[(size_t)d*SEQ + n0 + n4];
    }

    ull o2[8][3];
    float mx[8], l[8];
    #pragma unroll
    for (int i = 0; i < 8; ++i){
        mx[i] = -1e30f; l[i] = 0.f;
        o2[i][0] = 0ull; o2[i][1] = 0ull; o2[i][2] = 0ull;
    }

    #pragma unroll 1
    for (int t = 0; t < SEQ/128; ++t){
        __syncthreads();

        const int kn0 = t*128;
        #pragma unroll
        for (int it = 0; it < 12; ++it){
            int f  = tid + it*256;
            int d  = f >> 5;
            int n4 = (f & 31) << 2;
            *(float4*)&Ks[d*128 + n4] = *(const float4*)&Kg[(size_t)d*SEQ + kn0 + n4];
            int r  = f / 24;
            int d4 = (f % 24) << 2;
            *(float4*)&Vs[r*HDIM + d4] = *(const float4*)&Vg[(size_t)(kn0 + r)*HDIM + d4];
        }
        __syncthreads();

        ull s2[8][4];
        #pragma unroll
        for (int i = 0; i < 8; ++i)
            #pragma unroll
            for (int j = 0; j < 4; ++j) s2[i][j] = 0ull;

        #pragma unroll 4
        for (int k = 0; k < HDIM; ++k){
            float4 qa = *(float4*)&Qs[k*128 + 4*ty];
            float4 qb = *(float4*)&Qs[k*128 + 64 + 4*ty];
            ulonglong2 ka = *(const ulonglong2*)&Ks[k*128 + 4*tx];
            ulonglong2 kb = *(const ulonglong2*)&Ks[k*128 + 64 + 4*tx];
            float qv[8] = {qa.x, qa.y, qa.z, qa.w, qb.x, qb.y, qb.z, qb.w};
            #pragma unroll
            for (int i = 0; i < 8; ++i){
                ull qd = pack2(qv[i], qv[i]);
                s2[i][0] = fma2(qd, ka.x, s2[i][0]);
                s2[i][1] = fma2(qd, ka.y, s2[i][1]);
                s2[i][2] = fma2(qd, kb.x, s2[i][2]);
                s2[i][3] = fma2(qd, kb.y, s2[i][3]);
            }
        }

        #pragma unroll
        for (int i = 0; i < 8; ++i){
            float s[8];
            unpack2(s2[i][0], s[0], s[1]);
            unpack2(s2[i][1], s[2], s[3]);
            unpack2(s2[i][2], s[4], s[5]);
            unpack2(s2[i][3], s[6], s[7]);
            float tm = fmaxf(fmaxf(fmaxf(s[0], s[1]), fmaxf(s[2], s[3])),
                             fmaxf(fmaxf(s[4], s[5]), fmaxf(s[6], s[7])));
            #pragma unroll
            for (int off = 8; off > 0; off >>= 1)
                tm = fmaxf(tm, __shfl_xor_sync(0xffffffffu, tm, off, 16));
            const float mnew  = fmaxf(mx[i], tm);
            const float alpha = __expf(mx[i] - mnew);
            float p[8], rs = 0.f;
            #pragma unroll
            for (int u = 0; u < 8; ++u){ p[u] = __expf(s[u] - mnew); rs += p[u]; }
            #pragma unroll
            for (int off = 8; off > 0; off >>= 1)
                rs += __shfl_xor_sync(0xffffffffu, rs, off, 16);
            l[i] = l[i]*alpha + rs;
            mx[i] = mnew;
            const ull a2 = pack2(alpha, alpha);
            o2[i][0] = mul2(a2, o2[i][0]);
            o2[i][1] = mul2(a2, o2[i][1]);
            o2[i][2] = mul2(a2, o2[i][2]);
            *(float4*)&Ps[row8[i]*128 + 4*tx]      = make_float4(p[0], p[1], p[2], p[3]);
            *(float4*)&Ps[row8[i]*128 + 64 + 4*tx] = make_float4(p[4], p[5], p[6], p[7]);
        }
        __syncthreads();

        #pragma unroll 1
        for (int kk0 = 0; kk0 < 128; kk0 += 4){
            float4 pr[8];
            #pragma unroll
            for (int i = 0; i < 8; ++i)
                pr[i] = *(float4*)&Ps[row8[i]*128 + kk0];
            #pragma unroll
            for (int u = 0; u < 4; ++u){
                const int kk = kk0 + u;
                ull v0 = *(const ull*)&Vs[kk*HDIM + 2*tx];
                ull v1 = *(const ull*)&Vs[kk*HDIM + 2*tx + 32];
                ull v2 = *(const ull*)&Vs[kk*HDIM + 2*tx + 64];
                #pragma unroll
                for (int i = 0; i < 8; ++i){
                    const float pv = ((const float*)&pr[i])[u];
                    const ull pd = pack2(pv, pv);
                    o2[i][0] = fma2(pd, v0, o2[i][0]);
                    o2[i][1] = fma2(pd, v1, o2[i][1]);
                    o2[i][2] = fma2(pd, v2, o2[i][2]);
                }
            }
        }
    }

    const int b = bh / HEADS, h = bh % HEADS;
    #pragma unroll
    for (int i = 0; i < 8; ++i){
        const float sc = INV_SCALE / l[i];
        float* dst = g_attn + (size_t)(b*SEQ + n0 + row8[i])*EMB + h*HDIM;
        #pragma unroll
        for (int j = 0; j < 3; ++j){
            float lo, hi; unpack2(o2[i][j], lo, hi);
            dst[2*tx + 32*j + 0] = lo * sc;
            dst[2*tx + 32*j + 1] = hi * sc;
        }
    }
}

// ============================================================================
extern "C" void kernel_launch(void* const* d_in, const int* in_sizes, int n_in,
                              void* d_out, int out_size)
{
    const float* x      = (const float*)d_in[0];
    const float* w_qkv  = (const float*)d_in[1];
    const float* b_qkv  = (const float*)d_in[2];
    const float* w_proj = (const float*)d_in[3];
    const float* b_proj = (const float*)d_in[4];
    float* out = (float*)d_out;

    const int fl_smem = (96*128 + 96*128 + 128*96 + 128*128) * (int)sizeof(float); // 212992
    cudaFuncSetAttribute(flash_kernel, cudaFuncAttributeMaxDynamicSharedMemorySize, fl_smem);
    cudaFuncSetAttribute(gemm_mma<QKV_N, 0>, cudaFuncAttributeMaxDynamicSharedMemorySize, SG_SMEM);
    cudaFuncSetAttribute(gemm_mma<EMB, 1>,  cudaFuncAttributeMaxDynamicSharedMemorySize, SG_SMEM);

    // 1) QKV GEMM (mma.sync split-bf16) + bias + scatter
    gemm_mma<QKV_N, 0><<<dim3(QKV_N/128, ROWS/128), 256, SG_SMEM>>>(x, w_qkv, b_qkv, nullptr);
    // 2) flash attention (fp32 f32x2), 256 threads/block
    flash_kernel<<<dim3(SEQ/128, BATCH*HEADS), dim3(16, 16), fl_smem>>>();
    // 3) output projection (mma.sync split-bf16) + bias
    gemm_mma<EMB, 1><<<dim3(EMB/128, ROWS/128), 256, SG_SMEM>>>(nullptr, w_proj, b_proj, out);
}

// round 15
// speedup vs baseline: 1.0008x; 1.0008x over previous
#include <cuda_runtime.h>
#include <cuda_bf16.h>
#include <cstdint>

#define EMB   768
#define HEADS 8
#define HDIM  96
#define BATCH 4
#define SEQ   2048
#define ROWS  (BATCH*SEQ)      /* 8192 */
#define QKV_N (3*EMB)          /* 2304 */
#define INV_SCALE 0.10206207261596577f   /* 1/sqrt(96) */

typedef unsigned long long ull;

// ---------------- scratch (static device globals: allocation-free) ----------
__device__ float g_q[BATCH*HEADS*HDIM*SEQ];   // [bh][d][n]
__device__ float g_k[BATCH*HEADS*HDIM*SEQ];   // [bh][d][n]
__device__ float g_v[BATCH*HEADS*SEQ*HDIM];   // [bh][n][d]
__device__ float g_attn[ROWS*EMB];

// ---------------- f32x2 helpers (packed fp32, for flash) --------------------
__device__ __forceinline__ ull pack2(float lo, float hi){
    ull r; asm("mov.b64 %0, {%1, %2};" : "=l"(r) : "f"(lo), "f"(hi)); return r;
}
__device__ __forceinline__ void unpack2(ull v, float& lo, float& hi){
    asm("mov.b64 {%0, %1}, %2;" : "=f"(lo), "=f"(hi) : "l"(v));
}
__device__ __forceinline__ ull fma2(ull a, ull b, ull c){
    ull d; asm("fma.rn.f32x2 %0, %1, %2, %3;" : "=l"(d) : "l"(a), "l"(b), "l"(c)); return d;
}
__device__ __forceinline__ ull mul2(ull a, ull b){
    ull d; asm("mul.rn.f32x2 %0, %1, %2;" : "=l"(d) : "l"(a), "l"(b)); return d;
}

// ---------------- mma.sync helpers (Ampere-era PTX, valid on compute_103) ---
__device__ __forceinline__ uint32_t smem_u32(const void* p){
    uint32_t a;
    asm("{ .reg .u64 t; cvta.to.shared.u64 t, %1; cvt.u32.u64 %0, t; }" : "=r"(a) : "l"(p));
    return a;
}
#define LDM4(r, addr) \
    asm volatile("ldmatrix.sync.aligned.m8n8.x4.shared.b16 {%0,%1,%2,%3}, [%4];" \
        : "=r"((r)[0]), "=r"((r)[1]), "=r"((r)[2]), "=r"((r)[3]) : "r"(addr))

__device__ __forceinline__ void mma_bf16(float* c, const uint32_t* a, const uint32_t* b){
    asm volatile("mma.sync.aligned.m16n8k16.row.col.f32.bf16.bf16.f32 "
        "{%0,%1,%2,%3}, {%4,%5,%6,%7}, {%8,%9}, {%0,%1,%2,%3};"
        : "+f"(c[0]), "+f"(c[1]), "+f"(c[2]), "+f"(c[3])
        : "r"(a[0]), "r"(a[1]), "r"(a[2]), "r"(a[3]), "r"(b[0]), "r"(b[1]));
}

// split fp32 pair -> packed bf16x2 hi and lo  (bf16x3 decomposition)
__device__ __forceinline__ void split2(float a, float b, uint32_t& hi, uint32_t& lo){
    __nv_bfloat162 h = __floats2bfloat162_rn(a, b);
    float ra = a - __bfloat162float(h.x);
    float rb = b - __bfloat162float(h.y);
    __nv_bfloat162 l = __floats2bfloat162_rn(ra, rb);
    hi = *reinterpret_cast<uint32_t*>(&h);
    lo = *reinterpret_cast<uint32_t*>(&l);
}

// ============================================================================
// mma.sync split-bf16 GEMM: C[M x NC] = A[M x 768] * B[768 x NC] + bias
//   MODE 0: A = x, scatter into g_q/g_k (d-major) and g_v (n-major)
//   MODE 1: A = g_attn, dense write to C (= d_out)
// CTA tile 128x128, BK=64, 256 threads (8 warps: 4 in M x 2 in N;
// warp tile 32m x 64n = 2 m-frags x 8 n-frags of m16n8k16).
// SMEM: k-major rows of 64 bf16 (128B = 8x16B units), unit-XOR swizzle by
// (row&7) -> conflict-free for staging STS and ldmatrix.
// Per k16 step: 12 ldmatrix.x4, 48 HMMA (hi*hi + hi*lo + lo*hi).
// ============================================================================
#define SG_SMEM (64*1024 + 512)
template<int NC, int MODE>
__global__ void __launch_bounds__(256)
gemm_mma(const float* __restrict__ A, const float* __restrict__ B,
         const float* __restrict__ bias, float* __restrict__ C)
{
    extern __shared__ __align__(16) char smraw[];
    char* Ah = smraw;                 // 128 rows x 128B
    char* Al = smraw + 16384;
    char* Bh = smraw + 32768;         // 128 n-rows x 128B
    char* Bl = smraw + 49152;
    float* bs = (float*)(smraw + 65536);

    const uint32_t sb  = smem_u32(smraw);
    const uint32_t AhU = sb, AlU = sb + 16384u, BhU = sb + 32768u, BlU = sb + 49152u;

    const int tid  = threadIdx.x;
    const int wid  = tid >> 5;
    const int lane = tid & 31;
    const int wm   = wid & 3;         // warp row group (32 rows)
    const int wn   = wid >> 2;        // warp col group (64 cols)
    const int bx = blockIdx.x, by = blockIdx.y;

    const float* Asrc = (MODE == 0) ? A : (const float*)g_attn;
    const float* Ag = Asrc + (size_t)by*128*EMB;
    const float* Wg = B + bx*128;

    if (tid < 128) bs[tid] = bias[bx*128 + tid];

    float acc[2][8][4];
    #pragma unroll
    for (int i = 0; i < 2; ++i)
        #pragma unroll
        for (int j = 0; j < 8; ++j)
            #pragma unroll
            for (int e = 0; e < 4; ++e) acc[i][j][e] = 0.f;

    for (int c = 0; c < 12; ++c){
        const int c0 = c*64;
        __syncthreads();   // prev compute done reading smem (and bias STS order)

        // ---- stage A chunk: A[m][c0..c0+63] -> Ah/Al [m][k], swizzled ----
        #pragma unroll
        for (int it = 0; it < 8; ++it){
            int f = tid + it*256;             // 0..2047
            int m = f >> 4, kq = f & 15;      // kq: float4 index (k = 4kq)
            float4 v = *(const float4*)&Ag[(size_t)m*EMB + c0 + 4*kq];
            uint32_t h0, l0, h1, l1;
            split2(v.x, v.y, h0, l0);
            split2(v.z, v.w, h1, l1);
            int u   = kq >> 1;                // 16B unit
            int off = m*128 + (((u ^ (m & 7)))*16) + (kq & 1)*8;
            *(uint2*)(Ah + off) = make_uint2(h0, h1);
            *(uint2*)(Al + off) = make_uint2(l0, l1);
        }
        // ---- stage B chunk (transposed): w[c0+k][n] -> Bh/Bl [n][k], swizzled
        #pragma unroll
        for (int it = 0; it < 4; ++it){
            int t  = tid + it*256;            // 0..1023
            int kp = t >> 5, nq = t & 31;     // k = 2kp, n quad = 4nq
            const float* w0 = Wg + (size_t)(c0 + 2*kp)*NC + 4*nq;
            float4 f0 = *(const float4*)w0;
            float4 f1 = *(const float4*)(w0 + NC);
            const float* p0 = (const float*)&f0;
            const float* p1 = (const float*)&f1;
            #pragma unroll
            for (int e = 0; e < 4; ++e){
                uint32_t h, l;
                split2(p0[e], p1[e], h, l);   // packs (k, k+1) for this n
                int n = 4*nq + e;
                int k = 2*kp;
                int u = k >> 3;
                int off = n*128 + ((u ^ (n & 7))*16) + (k & 7)*2;
                *(uint32_t*)(Bh + off) = h;
                *(uint32_t*)(Bl + off) = l;
            }
        }
        __syncthreads();

        // ---- compute: 4 k16 steps ----
        #pragma unroll
        for (int ks = 0; ks < 4; ++ks){
            uint32_t a_h[2][4], a_l[2][4], b_h[8][2], b_l[8][2];
            #pragma unroll
            for (int fi = 0; fi < 2; ++fi){
                int row = wm*32 + fi*16 + (lane & 15);
                uint32_t byte = (uint32_t)row*128u +
                                (uint32_t)(((ks*2 + (lane >> 4)) ^ (row & 7))*16);
                LDM4(a_h[fi], AhU + byte);
                LDM4(a_l[fi], AlU + byte);
            }
            #pragma unroll
            for (int fp = 0; fp < 4; ++fp){
                int n = wn*64 + fp*16 + (lane & 15);
                uint32_t byte = (uint32_t)n*128u +
                                (uint32_t)(((ks*2 + (lane >> 4)) ^ (n & 7))*16);
                uint32_t th[4], tl[4];
                LDM4(th, BhU + byte);
                LDM4(tl, BlU + byte);
                b_h[2*fp][0]   = th[0]; b_h[2*fp][1]   = th[2];
                b_h[2*fp+1][0] = th[1]; b_h[2*fp+1][1] = th[3];
                b_l[2*fp][0]   = tl[0]; b_l[2*fp][1]   = tl[2];
                b_l[2*fp+1][0] = tl[1]; b_l[2*fp+1][1] = tl[3];
            }
            #pragma unroll
            for (int fi = 0; fi < 2; ++fi)
                #pragma unroll
                for (int fj = 0; fj < 8; ++fj){
                    mma_bf16(acc[fi][fj], a_h[fi], b_h[fj]);
                    mma_bf16(acc[fi][fj], a_h[fi], b_l[fj]);
                    mma_bf16(acc[fi][fj], a_l[fi], b_h[fj]);
                }
        }
    }

    // ---- epilogue ----
    const int lq = lane >> 2, lr = lane & 3;
    #pragma unroll
    for (int fi = 0; fi < 2; ++fi){
        #pragma unroll
        for (int fj = 0; fj < 8; ++fj){
            const float* cc = acc[fi][fj];
            const int lcol = wn*64 + fj*8 + lr*2;
            const int col0 = bx*128 + lcol;
            const int r0   = by*128 + wm*32 + fi*16 + lq;
            if (MODE == 1){
                float2 v0 = make_float2(cc[0] + bs[lcol], cc[1] + bs[lcol+1]);
                float2 v1 = make_float2(cc[2] + bs[lcol], cc[3] + bs[lcol+1]);
                *(float2*)&C[(size_t)r0*NC + col0]     = v0;
                *(float2*)&C[(size_t)(r0+8)*NC + col0] = v1;
            } else {
                #pragma unroll
                for (int h2 = 0; h2 < 2; ++h2){
                    const int m = r0 + 8*h2;
                    const int b = m >> 11, n = m & 2047;
                    #pragma unroll
                    for (int e = 0; e < 2; ++e){
                        const int ccol = col0 + e;
                        const float val = cc[2*h2 + e] + bs[lcol + e];
                        // qkv reshape (B,N,H,D,3): ccol = h*288 + d*3 + which
                        const int which = ccol % 3;
                        const int tt    = ccol / 3;
                        const int d     = tt % HDIM;
                        const int h     = tt / HDIM;
                        const int bh    = b*HEADS + h;
                        if (which == 2)
                            g_v[((size_t)bh*SEQ + n)*HDIM + d] = val;      // [bh][n][d]
                        else
                            ((which == 0) ? g_q : g_k)
                                [((size_t)bh*HDIM + d)*SEQ + n] = val;     // [bh][d][n]
                    }
                }
            }
        }
    }
}

// ============================================================================
// Flash attention (best measured config): fp32 online softmax, 256 threads,
// one block = (bh, 128-query tile), 8x8 micro-tile, f32x2 FMAs.
// softmax(S) applied, 1/sqrt(D) AFTER (faithful to reference).
// ============================================================================
__global__ void __launch_bounds__(256, 1) flash_kernel()
{
    extern __shared__ __align__(16) float smf[];
    float* Qs = smf;                 // [96][128]  k-major
    float* Ks = Qs + 96*128;         // [96][128]  k-major
    float* Vs = Ks + 96*128;         // [128][96]  n-major
    float* Ps = Vs + 128*96;         // [128][128] row-major

    const int tx = threadIdx.x, ty = threadIdx.y;
    const int tid = ty*16 + tx;
    const int n0 = blockIdx.x * 128;
    const int bh = blockIdx.y;

    const float* Qg = g_q + (size_t)bh*HDIM*SEQ;
    const float* Kg = g_k + (size_t)bh*HDIM*SEQ;
    const float* Vg = g_v + (size_t)bh*SEQ*HDIM;

    int row8[8];
    #pragma unroll
    for (int i = 0; i < 8; ++i) row8[i] = (i < 4) ? (4*ty + i) : (64 + 4*ty + i - 4);

    #pragma unroll
    for (int it = 0; it < 12; ++it){
        int f  = tid + it*256;
        int d  = f >> 5;
        int n4 = (f & 31) << 2;
        *(float4*)&Qs[d*128 + n4] = *(const float4*)&Qg[(size_t)d*SEQ + n0 + n4];
    }

    ull o2[8][3];
    float mx[8], l[8];
    #pragma unroll
    for (int i = 0; i < 8; ++i){
        mx[i] = -1e30f; l[i] = 0.f;
        o2[i][0] = 0ull; o2[i][1] = 0ull; o2[i][2] = 0ull;
    }

    #pragma unroll 1
    for (int t = 0; t < SEQ/128; ++t){
        __syncthreads();

        const int kn0 = t*128;
        #pragma unroll
        for (int it = 0; it < 12; ++it){
            int f  = tid + it*256;
            int d  = f >> 5;
            int n4 = (f & 31) << 2;
            *(float4*)&Ks[d*128 + n4] = *(const float4*)&Kg[(size_t)d*SEQ + kn0 + n4];
            int r  = f / 24;
            int d4 = (f % 24) << 2;
            *(float4*)&Vs[r*HDIM + d4] = *(const float4*)&Vg[(size_t)(kn0 + r)*HDIM + d4];
        }
        __syncthreads();

        ull s2[8][4];
        #pragma unroll
        for (int i = 0; i < 8; ++i)
            #pragma unroll
            for (int j = 0; j < 4; ++j) s2[i][j] = 0ull;

        #pragma unroll 4
        for (int k = 0; k < HDIM; ++k){
            float4 qa = *(float4*)&Qs[k*128 + 4*ty];
            float4 qb = *(float4*)&Qs[k*128 + 64 + 4*ty];
            ulonglong2 ka = *(const ulonglong2*)&Ks[k*128 + 4*tx];
            ulonglong2 kb = *(const ulonglong2*)&Ks[k*128 + 64 + 4*tx];
            float qv[8] = {qa.x, qa.y, qa.z, qa.w, qb.x, qb.y, qb.z, qb.w};
            #pragma unroll
            for (int i = 0; i < 8; ++i){
                ull qd = pack2(qv[i], qv[i]);
                s2[i][0] = fma2(qd, ka.x, s2[i][0]);
                s2[i][1] = fma2(qd, ka.y, s2[i][1]);
                s2[i][2] = fma2(qd, kb.x, s2[i][2]);
                s2[i][3] = fma2(qd, kb.y, s2[i][3]);
            }
        }

        #pragma unroll
        for (int i = 0; i < 8; ++i){
            float s[8];
            unpack2(s2[i][0], s[0], s[1]);
            unpack2(s2[i][1], s[2], s[3]);
            unpack2(s2[i][2], s[4], s[5]);
            unpack2(s2[i][3], s[6], s[7]);
            float tm = fmaxf(fmaxf(fmaxf(s[0], s[1]), fmaxf(s[2], s[3])),
                             fmaxf(fmaxf(s[4], s[5]), fmaxf(s[6], s[7])));
            #pragma unroll
            for (int off = 8; off > 0; off >>= 1)
                tm = fmaxf(tm, __shfl_xor_sync(0xffffffffu, tm, off, 16));
            const float mnew  = fmaxf(mx[i], tm);
            const float alpha = __expf(mx[i] - mnew);
            float p[8], rs = 0.f;
            #pragma unroll
            for (int u = 0; u < 8; ++u){ p[u] = __expf(s[u] - mnew); rs += p[u]; }
            #pragma unroll
            for (int off = 8; off > 0; off >>= 1)
                rs += __shfl_xor_sync(0xffffffffu, rs, off, 16);
            l[i] = l[i]*alpha + rs;
            mx[i] = mnew;
            const ull a2 = pack2(alpha, alpha);
            o2[i][0] = mul2(a2, o2[i][0]);
            o2[i][1] = mul2(a2, o2[i][1]);
            o2[i][2] = mul2(a2, o2[i][2]);
            *(float4*)&Ps[row8[i]*128 + 4*tx]      = make_float4(p[0], p[1], p[2], p[3]);
            *(float4*)&Ps[row8[i]*128 + 64 + 4*tx] = make_float4(p[4], p[5], p[6], p[7]);
        }
        __syncthreads();

        #pragma unroll 1
        for (int kk0 = 0; kk0 < 128; kk0 += 4){
            float4 pr[8];
            #pragma unroll
            for (int i = 0; i < 8; ++i)
                pr[i] = *(float4*)&Ps[row8[i]*128 + kk0];
            #pragma unroll
            for (int u = 0; u < 4; ++u){
                const int kk = kk0 + u;
                ull v0 = *(const ull*)&Vs[kk*HDIM + 2*tx];
                ull v1 = *(const ull*)&Vs[kk*HDIM + 2*tx + 32];
                ull v2 = *(const ull*)&Vs[kk*HDIM + 2*tx + 64];
                #pragma unroll
                for (int i = 0; i < 8; ++i){
                    const float pv = ((const float*)&pr[i])[u];
                    const ull pd = pack2(pv, pv);
                    o2[i][0] = fma2(pd, v0, o2[i][0]);
                    o2[i][1] = fma2(pd, v1, o2[i][1]);
                    o2[i][2] = fma2(pd, v2, o2[i][2]);
                }
            }
        }
    }

    const int b = bh / HEADS, h = bh % HEADS;
    #pragma unroll
    for (int i = 0; i < 8; ++i){
        const float sc = INV_SCALE / l[i];
        float* dst = g_attn + (size_t)(b*SEQ + n0 + row8[i])*EMB + h*HDIM;
        #pragma unroll
        for (int j = 0; j < 3; ++j){
            float lo, hi; unpack2(o2[i][j], lo, hi);
            dst[2*tx + 32*j + 0] = lo * sc;
            dst[2*tx + 32*j + 1] = hi * sc;
        }
    }
}

// ============================================================================
extern "C" void kernel_launch(void* const* d_in, const int* in_sizes, int n_in,
                              void* d_out, int out_size)
{
    const float* x      = (const float*)d_in[0];
    const float* w_qkv  = (const float*)d_in[1];
    const float* b_qkv  = (const float*)d_in[2];
    const float* w_proj = (const float*)d_in[3];
    const float* b_proj = (const float*)d_in[4];
    float* out = (float*)d_out;

    const int fl_smem = (96*128 + 96*128 + 128*96 + 128*128) * (int)sizeof(float); // 212992
    cudaFuncSetAttribute(flash_kernel, cudaFuncAttributeMaxDynamicSharedMemorySize, fl_smem);
    cudaFuncSetAttribute(gemm_mma<QKV_N, 0>, cudaFuncAttributeMaxDynamicSharedMemorySize, SG_SMEM);
    cudaFuncSetAttribute(gemm_mma<EMB, 1>,  cudaFuncAttributeMaxDynamicSharedMemorySize, SG_SMEM);

    // 1) QKV GEMM (mma.sync split-bf16) + bias + scatter
    gemm_mma<QKV_N, 0><<<dim3(QKV_N/128, ROWS/128), 256, SG_SMEM>>>(x, w_qkv, b_qkv, nullptr);
    // 2) flash attention (fp32 f32x2), 256 threads/block
    flash_kernel<<<dim3(SEQ/128, BATCH*HEADS), dim3(16, 16), fl_smem>>>();
    // 3) output projection (mma.sync split-bf16) + bias
    gemm_mma<EMB, 1><<<dim3(EMB/128, ROWS/128), 256, SG_SMEM>>>(nullptr, w_proj, b_proj, out);
}

// round 16
// speedup vs baseline: 1.0014x; 1.0006x over previous
#include <cuda_runtime.h>
#include <cuda_bf16.h>
#include <cstdint>

#define EMB   768
#define HEADS 8
#define HDIM  96
#define BATCH 4
#define SEQ   2048
#define ROWS  (BATCH*SEQ)      /* 8192 */
#define QKV_N (3*EMB)          /* 2304 */
#define INV_SCALE 0.10206207261596577f   /* 1/sqrt(96) */

typedef unsigned long long ull;

// ---------------- scratch (static device globals: allocation-free) ----------
__device__ float g_q[BATCH*HEADS*HDIM*SEQ];   // [bh][d][n]
__device__ float g_k[BATCH*HEADS*HDIM*SEQ];   // [bh][d][n]
__device__ float g_v[BATCH*HEADS*SEQ*HDIM];   // [bh][n][d]
__device__ float g_attn[ROWS*EMB];

// ---------------- f32x2 helpers (packed fp32, for flash) --------------------
__device__ __forceinline__ ull pack2(float lo, float hi){
    ull r; asm("mov.b64 %0, {%1, %2};" : "=l"(r) : "f"(lo), "f"(hi)); return r;
}
__device__ __forceinline__ void unpack2(ull v, float& lo, float& hi){
    asm("mov.b64 {%0, %1}, %2;" : "=f"(lo), "=f"(hi) : "l"(v));
}
__device__ __forceinline__ ull fma2(ull a, ull b, ull c){
    ull d; asm("fma.rn.f32x2 %0, %1, %2, %3;" : "=l"(d) : "l"(a), "l"(b), "l"(c)); return d;
}
__device__ __forceinline__ ull mul2(ull a, ull b){
    ull d; asm("mul.rn.f32x2 %0, %1, %2;" : "=l"(d) : "l"(a), "l"(b)); return d;
}

// ---------------- mma.sync helpers (Ampere-era PTX, valid on compute_103) ---
__device__ __forceinline__ uint32_t smem_u32(const void* p){
    uint32_t a;
    asm("{ .reg .u64 t; cvta.to.shared.u64 t, %1; cvt.u32.u64 %0, t; }" : "=r"(a) : "l"(p));
    return a;
}
#define LDM4(r, addr) \
    asm volatile("ldmatrix.sync.aligned.m8n8.x4.shared.b16 {%0,%1,%2,%3}, [%4];" \
        : "=r"((r)[0]), "=r"((r)[1]), "=r"((r)[2]), "=r"((r)[3]) : "r"(addr))

__device__ __forceinline__ void mma_bf16(float* c, const uint32_t* a, const uint32_t* b){
    asm volatile("mma.sync.aligned.m16n8k16.row.col.f32.bf16.bf16.f32 "
        "{%0,%1,%2,%3}, {%4,%5,%6,%7}, {%8,%9}, {%0,%1,%2,%3};"
        : "+f"(c[0]), "+f"(c[1]), "+f"(c[2]), "+f"(c[3])
        : "r"(a[0]), "r"(a[1]), "r"(a[2]), "r"(a[3]), "r"(b[0]), "r"(b[1]));
}

// split fp32 pair -> packed bf16x2 hi and lo  (bf16x3 decomposition)
__device__ __forceinline__ void split2(float a, float b, uint32_t& hi, uint32_t& lo){
    __nv_bfloat162 h = __floats2bfloat162_rn(a, b);
    float ra = a - __bfloat162float(h.x);
    float rb = b - __bfloat162float(h.y);
    __nv_bfloat162 l = __floats2bfloat162_rn(ra, rb);
    hi = *reinterpret_cast<uint32_t*>(&h);
    lo = *reinterpret_cast<uint32_t*>(&l);
}

// ============================================================================
// mma.sync split-bf16 GEMM: C[M x NC] = A[M x 768] * B[768 x NC] + bias
//   MODE 0: A = x, scatter into g_q/g_k (d-major) and g_v (n-major)
//   MODE 1: A = g_attn, dense write to C (= d_out)
// CTA tile 128x128, BK=64, 256 threads (8 warps: 4 in M x 2 in N;
// warp tile 32m x 64n = 2 m-frags x 8 n-frags of m16n8k16).
// SMEM: k-major rows of 64 bf16 (128B = 8x16B units), unit-XOR swizzle by
// (row&7) -> conflict-free for staging STS and ldmatrix.
// Per k16 step: 12 ldmatrix.x4, 48 HMMA (hi*hi + hi*lo + lo*hi).
// ============================================================================
#define SG_SMEM (64*1024 + 512)
template<int NC, int MODE>
__global__ void __launch_bounds__(256)
gemm_mma(const float* __restrict__ A, const float* __restrict__ B,
         const float* __restrict__ bias, float* __restrict__ C)
{
    extern __shared__ __align__(16) char smraw[];
    char* Ah = smraw;                 // 128 rows x 128B
    char* Al = smraw + 16384;
    char* Bh = smraw + 32768;         // 128 n-rows x 128B
    char* Bl = smraw + 49152;
    float* bs = (float*)(smraw + 65536);

    const uint32_t sb  = smem_u32(smraw);
    const uint32_t AhU = sb, AlU = sb + 16384u, BhU = sb + 32768u, BlU = sb + 49152u;

    const int tid  = threadIdx.x;
    const int wid  = tid >> 5;
    const int lane = tid & 31;
    const int wm   = wid & 3;         // warp row group (32 rows)
    const int wn   = wid >> 2;        // warp col group (64 cols)
    const int bx = blockIdx.x, by = blockIdx.y;

    const float* Asrc = (MODE == 0) ? A : (const float*)g_attn;
    const float* Ag = Asrc + (size_t)by*128*EMB;
    const float* Wg = B + bx*128;

    if (tid < 128) bs[tid] = bias[bx*128 + tid];

    float acc[2][8][4];
    #pragma unroll
    for (int i = 0; i < 2; ++i)
        #pragma unroll
        for (int j = 0; j < 8; ++j)
            #pragma unroll
            for (int e = 0; e < 4; ++e) acc[i][j][e] = 0.f;

    for (int c = 0; c < 12; ++c){
        const int c0 = c*64;
        __syncthreads();   // prev compute done reading smem (and bias STS order)

        // ---- stage A chunk: A[m][c0..c0+63] -> Ah/Al [m][k], swizzled ----
        #pragma unroll
        for (int it = 0; it < 8; ++it){
            int f = tid + it*256;             // 0..2047
            int m = f >> 4, kq = f & 15;      // kq: float4 index (k = 4kq)
            float4 v = *(const float4*)&Ag[(size_t)m*EMB + c0 + 4*kq];
            uint32_t h0, l0, h1, l1;
            split2(v.x, v.y, h0, l0);
            split2(v.z, v.w, h1, l1);
            int u   = kq >> 1;                // 16B unit
            int off = m*128 + (((u ^ (m & 7)))*16) + (kq & 1)*8;
            *(uint2*)(Ah + off) = make_uint2(h0, h1);
            *(uint2*)(Al + off) = make_uint2(l0, l1);
        }
        // ---- stage B chunk (transposed): w[c0+k][n] -> Bh/Bl [n][k], swizzled
        #pragma unroll
        for (int it = 0; it < 4; ++it){
            int t  = tid + it*256;            // 0..1023
            int kp = t >> 5, nq = t & 31;     // k = 2kp, n quad = 4nq
            const float* w0 = Wg + (size_t)(c0 + 2*kp)*NC + 4*nq;
            float4 f0 = *(const float4*)w0;
            float4 f1 = *(const float4*)(w0 + NC);
            const float* p0 = (const float*)&f0;
            const float* p1 = (const float*)&f1;
            #pragma unroll
            for (int e = 0; e < 4; ++e){
                uint32_t h, l;
                split2(p0[e], p1[e], h, l);   // packs (k, k+1) for this n
                int n = 4*nq + e;
                int k = 2*kp;
                int u = k >> 3;
                int off = n*128 + ((u ^ (n & 7))*16) + (k & 7)*2;
                *(uint32_t*)(Bh + off) = h;
                *(uint32_t*)(Bl + off) = l;
            }
        }
        __syncthreads();

        // ---- compute: 4 k16 steps ----
        #pragma unroll
        for (int ks = 0; ks < 4; ++ks){
            uint32_t a_h[2][4], a_l[2][4], b_h[8][2], b_l[8][2];
            #pragma unroll
            for (int fi = 0; fi < 2; ++fi){
                int row = wm*32 + fi*16 + (lane & 15);
                uint32_t byte = (uint32_t)row*128u +
                                (uint32_t)(((ks*2 + (lane >> 4)) ^ (row & 7))*16);
                LDM4(a_h[fi], AhU + byte);
                LDM4(a_l[fi], AlU + byte);
            }
            #pragma unroll
            for (int fp = 0; fp < 4; ++fp){
                int n = wn*64 + fp*16 + (lane & 15);
                uint32_t byte = (uint32_t)n*128u +
                                (uint32_t)(((ks*2 + (lane >> 4)) ^ (n & 7))*16);
                uint32_t th[4], tl[4];
                LDM4(th, BhU + byte);
                LDM4(tl, BlU + byte);
                b_h[2*fp][0]   = th[0]; b_h[2*fp][1]   = th[2];
                b_h[2*fp+1][0] = th[1]; b_h[2*fp+1][1] = th[3];
                b_l[2*fp][0]   = tl[0]; b_l[2*fp][1]   = tl[2];
                b_l[2*fp+1][0] = tl[1]; b_l[2*fp+1][1] = tl[3];
            }
            #pragma unroll
            for (int fi = 0; fi < 2; ++fi)
                #pragma unroll
                for (int fj = 0; fj < 8; ++fj){
                    mma_bf16(acc[fi][fj], a_h[fi], b_h[fj]);
                    mma_bf16(acc[fi][fj], a_h[fi], b_l[fj]);
                    mma_bf16(acc[fi][fj], a_l[fi], b_h[fj]);
                }
        }
    }

    // ---- epilogue ----
    const int lq = lane >> 2, lr = lane & 3;
    #pragma unroll
    for (int fi = 0; fi < 2; ++fi){
        #pragma unroll
        for (int fj = 0; fj < 8; ++fj){
            const float* cc = acc[fi][fj];
            const int lcol = wn*64 + fj*8 + lr*2;
            const int col0 = bx*128 + lcol;
            const int r0   = by*128 + wm*32 + fi*16 + lq;
            if (MODE == 1){
                float2 v0 = make_float2(cc[0] + bs[lcol], cc[1] + bs[lcol+1]);
                float2 v1 = make_float2(cc[2] + bs[lcol], cc[3] + bs[lcol+1]);
                *(float2*)&C[(size_t)r0*NC + col0]     = v0;
                *(float2*)&C[(size_t)(r0+8)*NC + col0] = v1;
            } else {
                #pragma unroll
                for (int h2 = 0; h2 < 2; ++h2){
                    const int m = r0 + 8*h2;
                    const int b = m >> 11, n = m & 2047;
                    #pragma unroll
                    for (int e = 0; e < 2; ++e){
                        const int ccol = col0 + e;
                        const float val = cc[2*h2 + e] + bs[lcol + e];
                        // qkv reshape (B,N,H,D,3): ccol = h*288 + d*3 + which
                        const int which = ccol % 3;
                        const int tt    = ccol / 3;
                        const int d     = tt % HDIM;
                        const int h     = tt / HDIM;
                        const int bh    = b*HEADS + h;
                        if (which == 2)
                            g_v[((size_t)bh*SEQ + n)*HDIM + d] = val;      // [bh][n][d]
                        else
                            ((which == 0) ? g_q : g_k)
                                [((size_t)bh*HDIM + d)*SEQ + n] = val;     // [bh][d][n]
                    }
                }
            }
        }
    }
}

// ============================================================================
// Flash attention (best measured config): fp32 online softmax, 256 threads,
// one block = (bh, 128-query tile), 8x8 micro-tile, f32x2 FMAs.
// softmax(S) applied, 1/sqrt(D) AFTER (faithful to reference).
// ============================================================================
__global__ void __launch_bounds__(256, 1) flash_kernel()
{
    extern __shared__ __align__(16) float smf[];
    float* Qs = smf;                 // [96][128]  k-major
    float* Ks = Qs + 96*128;         // [96][128]  k-major
    float* Vs = Ks + 96*128;         // [128][96]  n-major
    float* Ps = Vs + 128*96;         // [128][128] row-major

    const int tx = threadIdx.x, ty = threadIdx.y;
    const int tid = ty*16 + tx;
    const int n0 = blockIdx.x * 128;
    const int bh = blockIdx.y;

    const float* Qg = g_q + (size_t)bh*HDIM*SEQ;
    const float* Kg = g_k + (size_t)bh*HDIM*SEQ;
    const float* Vg = g_v + (size_t)bh*SEQ*HDIM;

    int row8[8];
    #pragma unroll
    for (int i = 0; i < 8; ++i) row8[i] = (i < 4) ? (4*ty + i) : (64 + 4*ty + i - 4);

    #pragma unroll
    for (int it = 0; it < 12; ++it){
        int f  = tid + it*256;
        int d  = f >> 5;
        int n4 = (f & 31) << 2;
        *(float4*)&Qs[d*128 + n4] = *(const float4*)&Qg[(size_t)d*SEQ + n0 + n4];
    }

    ull o2[8][3];
    float mx[8], l[8];
    #pragma unroll
    for (int i = 0; i < 8; ++i){
        mx[i] = -1e30f; l[i] = 0.f;
        o2[i][0] = 0ull; o2[i][1] = 0ull; o2[i][2] = 0ull;
    }

    #pragma unroll 1
    for (int t = 0; t < SEQ/128; ++t){
        __syncthreads();

        const int kn0 = t*128;
        #pragma unroll
        for (int it = 0; it < 12; ++it){
            int f  = tid + it*256;
            int d  = f >> 5;
            int n4 = (f & 31) << 2;
            *(float4*)&Ks[d*128 + n4] = *(const float4*)&Kg[(size_t)d*SEQ + kn0 + n4];
            int r  = f / 24;
            int d4 = (f % 24) << 2;
            *(float4*)&Vs[r*HDIM + d4] = *(const float4*)&Vg[(size_t)(kn0 + r)*HDIM + d4];
        }
        __syncthreads();

        ull s2[8][4];
        #pragma unroll
        for (int i = 0; i < 8; ++i)
            #pragma unroll
            for (int j = 0; j < 4; ++j) s2[i][j] = 0ull;

        #pragma unroll 4
        for (int k = 0; k < HDIM; ++k){
            float4 qa = *(float4*)&Qs[k*128 + 4*ty];
            float4 qb = *(float4*)&Qs[k*128 + 64 + 4*ty];
            ulonglong2 ka = *(const ulonglong2*)&Ks[k*128 + 4*tx];
            ulonglong2 kb = *(const ulonglong2*)&Ks[k*128 + 64 + 4*tx];
            float qv[8] = {qa.x, qa.y, qa.z, qa.w, qb.x, qb.y, qb.z, qb.w};
            #pragma unroll
            for (int i = 0; i < 8; ++i){
                ull qd = pack2(qv[i], qv[i]);
                s2[i][0] = fma2(qd, ka.x, s2[i][0]);
                s2[i][1] = fma2(qd, ka.y, s2[i][1]);
                s2[i][2] = fma2(qd, kb.x, s2[i][2]);
                s2[i][3] = fma2(qd, kb.y, s2[i][3]);
            }
        }

        #pragma unroll
        for (int i = 0; i < 8; ++i){
            float s[8];
            unpack2(s2[i][0], s[0], s[1]);
            unpack2(s2[i][1], s[2], s[3]);
            unpack2(s2[i][2], s[4], s[5]);
            unpack2(s2[i][3], s[6], s[7]);
            float tm = fmaxf(fmaxf(fmaxf(s[0], s[1]), fmaxf(s[2], s[3])),
                             fmaxf(fmaxf(s[4], s[5]), fmaxf(s[6], s[7])));
            #pragma unroll
            for (int off = 8; off > 0; off >>= 1)
                tm = fmaxf(tm, __shfl_xor_sync(0xffffffffu, tm, off, 16));
            const float mnew  = fmaxf(mx[i], tm);
            const float alpha = __expf(mx[i] - mnew);
            float p[8], rs = 0.f;
            #pragma unroll
            for (int u = 0; u < 8; ++u){ p[u] = __expf(s[u] - mnew); rs += p[u]; }
            #pragma unroll
            for (int off = 8; off > 0; off >>= 1)
                rs += __shfl_xor_sync(0xffffffffu, rs, off, 16);
            l[i] = l[i]*alpha + rs;
            mx[i] = mnew;
            const ull a2 = pack2(alpha, alpha);
            o2[i][0] = mul2(a2, o2[i][0]);
            o2[i][1] = mul2(a2, o2[i][1]);
            o2[i][2] = mul2(a2, o2[i][2]);
            *(float4*)&Ps[row8[i]*128 + 4*tx]      = make_float4(p[0], p[1], p[2], p[3]);
            *(float4*)&Ps[row8[i]*128 + 64 + 4*tx] = make_float4(p[4], p[5], p[6], p[7]);
        }
        __syncthreads();

        #pragma unroll 1
        for (int kk0 = 0; kk0 < 128; kk0 += 4){
            float4 pr[8];
            #pragma unroll
            for (int i = 0; i < 8; ++i)
                pr[i] = *(float4*)&Ps[row8[i]*128 + kk0];
            #pragma unroll
            for (int u = 0; u < 4; ++u){
                const int kk = kk0 + u;
                ull v0 = *(const ull*)&Vs[kk*HDIM + 2*tx];
                ull v1 = *(const ull*)&Vs[kk*HDIM + 2*tx + 32];
                ull v2 = *(const ull*)&Vs[kk*HDIM + 2*tx + 64];
                #pragma unroll
                for (int i = 0; i < 8; ++i){
                    const float pv = ((const float*)&pr[i])[u];
                    const ull pd = pack2(pv, pv);
                    o2[i][0] = fma2(pd, v0, o2[i][0]);
                    o2[i][1] = fma2(pd, v1, o2[i][1]);
                    o2[i][2] = fma2(pd, v2, o2[i][2]);
                }
            }
        }
    }

    const int b = bh / HEADS, h = bh % HEADS;
    #pragma unroll
    for (int i = 0; i < 8; ++i){
        const float sc = INV_SCALE / l[i];
        float* dst = g_attn + (size_t)(b*SEQ + n0 + row8[i])*EMB + h*HDIM;
        #pragma unroll
        for (int j = 0; j < 3; ++j){
            float lo, hi; unpack2(o2[i][j], lo, hi);
            dst[2*tx + 32*j + 0] = lo * sc;
            dst[2*tx + 32*j + 1] = hi * sc;
        }
    }
}

// ============================================================================
extern "C" void kernel_launch(void* const* d_in, const int* in_sizes, int n_in,
                              void* d_out, int out_size)
{
    const float* x      = (const float*)d_in[0];
    const float* w_qkv  = (const float*)d_in[1];
    const float* b_qkv  = (const float*)d_in[2];
    const float* w_proj = (const float*)d_in[3];
    const float* b_proj = (const float*)d_in[4];
    float* out = (float*)d_out;

    const int fl_smem = (96*128 + 96*128 + 128*96 + 128*128) * (int)sizeof(float); // 212992
    cudaFuncSetAttribute(flash_kernel, cudaFuncAttributeMaxDynamicSharedMemorySize, fl_smem);
    cudaFuncSetAttribute(gemm_mma<QKV_N, 0>, cudaFuncAttributeMaxDynamicSharedMemorySize, SG_SMEM);
    cudaFuncSetAttribute(gemm_mma<EMB, 1>,  cudaFuncAttributeMaxDynamicSharedMemorySize, SG_SMEM);

    // 1) QKV GEMM (mma.sync split-bf16) + bias + scatter
    gemm_mma<QKV_N, 0><<<dim3(QKV_N/128, ROWS/128), 256, SG_SMEM>>>(x, w_qkv, b_qkv, nullptr);
    // 2) flash attention (fp32 f32x2), 256 threads/block
    flash_kernel<<<dim3(SEQ/128, BATCH*HEADS), dim3(16, 16), fl_smem>>>();
    // 3) output projection (mma.sync split-bf16) + bias
    gemm_mma<EMB, 1><<<dim3(EMB/128, ROWS/128), 256, SG_SMEM>>>(nullptr, w_proj, b_proj, out);
}

// round 17
// speedup vs baseline: 1.0033x; 1.0019x over previous
#include <cuda_runtime.h>
#include <cuda_bf16.h>
#include <cstdint>

#define EMB   768
#define HEADS 8
#define HDIM  96
#define BATCH 4
#define SEQ   2048
#define ROWS  (BATCH*SEQ)      /* 8192 */
#define QKV_N (3*EMB)          /* 2304 */
#define INV_SCALE 0.10206207261596577f   /* 1/sqrt(96) */

typedef unsigned long long ull;

// ---------------- scratch (static device globals: allocation-free) ----------
__device__ float g_q[BATCH*HEADS*HDIM*SEQ];   // [bh][d][n]
__device__ float g_k[BATCH*HEADS*HDIM*SEQ];   // [bh][d][n]
__device__ float g_v[BATCH*HEADS*SEQ*HDIM];   // [bh][n][d]
__device__ float g_attn[ROWS*EMB];

// ---------------- f32x2 helpers (packed fp32, for flash) --------------------
__device__ __forceinline__ ull pack2(float lo, float hi){
    ull r; asm("mov.b64 %0, {%1, %2};" : "=l"(r) : "f"(lo), "f"(hi)); return r;
}
__device__ __forceinline__ void unpack2(ull v, float& lo, float& hi){
    asm("mov.b64 {%0, %1}, %2;" : "=f"(lo), "=f"(hi) : "l"(v));
}
__device__ __forceinline__ ull fma2(ull a, ull b, ull c){
    ull d; asm("fma.rn.f32x2 %0, %1, %2, %3;" : "=l"(d) : "l"(a), "l"(b), "l"(c)); return d;
}
__device__ __forceinline__ ull mul2(ull a, ull b){
    ull d; asm("mul.rn.f32x2 %0, %1, %2;" : "=l"(d) : "l"(a), "l"(b)); return d;
}

// ---------------- mma.sync helpers (Ampere-era PTX, valid on compute_103) ---
__device__ __forceinline__ uint32_t smem_u32(const void* p){
    uint32_t a;
    asm("{ .reg .u64 t; cvta.to.shared.u64 t, %1; cvt.u32.u64 %0, t; }" : "=r"(a) : "l"(p));
    return a;
}
#define LDM4(r, addr) \
    asm volatile("ldmatrix.sync.aligned.m8n8.x4.shared.b16 {%0,%1,%2,%3}, [%4];" \
        : "=r"((r)[0]), "=r"((r)[1]), "=r"((r)[2]), "=r"((r)[3]) : "r"(addr))

__device__ __forceinline__ void mma_bf16(float* c, const uint32_t* a, const uint32_t* b){
    asm volatile("mma.sync.aligned.m16n8k16.row.col.f32.bf16.bf16.f32 "
        "{%0,%1,%2,%3}, {%4,%5,%6,%7}, {%8,%9}, {%0,%1,%2,%3};"
        : "+f"(c[0]), "+f"(c[1]), "+f"(c[2]), "+f"(c[3])
        : "r"(a[0]), "r"(a[1]), "r"(a[2]), "r"(a[3]), "r"(b[0]), "r"(b[1]));
}

// split fp32 pair -> packed bf16x2 hi and lo  (bf16x3 decomposition)
__device__ __forceinline__ void split2(float a, float b, uint32_t& hi, uint32_t& lo){
    __nv_bfloat162 h = __floats2bfloat162_rn(a, b);
    float ra = a - __bfloat162float(h.x);
    float rb = b - __bfloat162float(h.y);
    __nv_bfloat162 l = __floats2bfloat162_rn(ra, rb);
    hi = *reinterpret_cast<uint32_t*>(&h);
    lo = *reinterpret_cast<uint32_t*>(&l);
}

// ============================================================================
// mma.sync split-bf16 GEMM: C[M x NC] = A[M x 768] * B[768 x NC] + bias
//   MODE 0: A = x, scatter into g_q/g_k (d-major) and g_v (n-major)
//   MODE 1: A = g_attn, dense write to C (= d_out)
// CTA tile 128x128, BK=64, 256 threads (8 warps: 4 in M x 2 in N;
// warp tile 32m x 64n = 2 m-frags x 8 n-frags of m16n8k16).
// SMEM: k-major rows of 64 bf16 (128B = 8x16B units), unit-XOR swizzle by
// (row&7) -> conflict-free for staging STS and ldmatrix.
// Per k16 step: 12 ldmatrix.x4, 48 HMMA (hi*hi + hi*lo + lo*hi).
// ============================================================================
#define SG_SMEM (64*1024 + 512)
template<int NC, int MODE>
__global__ void __launch_bounds__(256)
gemm_mma(const float* __restrict__ A, const float* __restrict__ B,
         const float* __restrict__ bias, float* __restrict__ C)
{
    extern __shared__ __align__(16) char smraw[];
    char* Ah = smraw;                 // 128 rows x 128B
    char* Al = smraw + 16384;
    char* Bh = smraw + 32768;         // 128 n-rows x 128B
    char* Bl = smraw + 49152;
    float* bs = (float*)(smraw + 65536);

    const uint32_t sb  = smem_u32(smraw);
    const uint32_t AhU = sb, AlU = sb + 16384u, BhU = sb + 32768u, BlU = sb + 49152u;

    const int tid  = threadIdx.x;
    const int wid  = tid >> 5;
    const int lane = tid & 31;
    const int wm   = wid & 3;         // warp row group (32 rows)
    const int wn   = wid >> 2;        // warp col group (64 cols)
    const int bx = blockIdx.x, by = blockIdx.y;

    const float* Asrc = (MODE == 0) ? A : (const float*)g_attn;
    const float* Ag = Asrc + (size_t)by*128*EMB;
    const float* Wg = B + bx*128;

    if (tid < 128) bs[tid] = bias[bx*128 + tid];

    float acc[2][8][4];
    #pragma unroll
    for (int i = 0; i < 2; ++i)
        #pragma unroll
        for (int j = 0; j < 8; ++j)
            #pragma unroll
            for (int e = 0; e < 4; ++e) acc[i][j][e] = 0.f;

    for (int c = 0; c < 12; ++c){
        const int c0 = c*64;
        __syncthreads();   // prev compute done reading smem (and bias STS order)

        // ---- stage A chunk: A[m][c0..c0+63] -> Ah/Al [m][k], swizzled ----
        #pragma unroll
        for (int it = 0; it < 8; ++it){
            int f = tid + it*256;             // 0..2047
            int m = f >> 4, kq = f & 15;      // kq: float4 index (k = 4kq)
            float4 v = *(const float4*)&Ag[(size_t)m*EMB + c0 + 4*kq];
            uint32_t h0, l0, h1, l1;
            split2(v.x, v.y, h0, l0);
            split2(v.z, v.w, h1, l1);
            int u   = kq >> 1;                // 16B unit
            int off = m*128 + (((u ^ (m & 7)))*16) + (kq & 1)*8;
            *(uint2*)(Ah + off) = make_uint2(h0, h1);
            *(uint2*)(Al + off) = make_uint2(l0, l1);
        }
        // ---- stage B chunk (transposed): w[c0+k][n] -> Bh/Bl [n][k], swizzled
        #pragma unroll
        for (int it = 0; it < 4; ++it){
            int t  = tid + it*256;            // 0..1023
            int kp = t >> 5, nq = t & 31;     // k = 2kp, n quad = 4nq
            const float* w0 = Wg + (size_t)(c0 + 2*kp)*NC + 4*nq;
            float4 f0 = *(const float4*)w0;
            float4 f1 = *(const float4*)(w0 + NC);
            const float* p0 = (const float*)&f0;
            const float* p1 = (const float*)&f1;
            #pragma unroll
            for (int e = 0; e < 4; ++e){
                uint32_t h, l;
                split2(p0[e], p1[e], h, l);   // packs (k, k+1) for this n
                int n = 4*nq + e;
                int k = 2*kp;
                int u = k >> 3;
                int off = n*128 + ((u ^ (n & 7))*16) + (k & 7)*2;
                *(uint32_t*)(Bh + off) = h;
                *(uint32_t*)(Bl + off) = l;
            }
        }
        __syncthreads();

        // ---- compute: 4 k16 steps ----
        #pragma unroll
        for (int ks = 0; ks < 4; ++ks){
            uint32_t a_h[2][4], a_l[2][4], b_h[8][2], b_l[8][2];
            #pragma unroll
            for (int fi = 0; fi < 2; ++fi){
                int row = wm*32 + fi*16 + (lane & 15);
                uint32_t byte = (uint32_t)row*128u +
                                (uint32_t)(((ks*2 + (lane >> 4)) ^ (row & 7))*16);
                LDM4(a_h[fi], AhU + byte);
                LDM4(a_l[fi], AlU + byte);
            }
            #pragma unroll
            for (int fp = 0; fp < 4; ++fp){
                int n = wn*64 + fp*16 + (lane & 15);
                uint32_t byte = (uint32_t)n*128u +
                                (uint32_t)(((ks*2 + (lane >> 4)) ^ (n & 7))*16);
                uint32_t th[4], tl[4];
                LDM4(th, BhU + byte);
                LDM4(tl, BlU + byte);
                b_h[2*fp][0]   = th[0]; b_h[2*fp][1]   = th[2];
                b_h[2*fp+1][0] = th[1]; b_h[2*fp+1][1] = th[3];
                b_l[2*fp][0]   = tl[0]; b_l[2*fp][1]   = tl[2];
                b_l[2*fp+1][0] = tl[1]; b_l[2*fp+1][1] = tl[3];
            }
            #pragma unroll
            for (int fi = 0; fi < 2; ++fi)
                #pragma unroll
                for (int fj = 0; fj < 8; ++fj){
                    mma_bf16(acc[fi][fj], a_h[fi], b_h[fj]);
                    mma_bf16(acc[fi][fj], a_h[fi], b_l[fj]);
                    mma_bf16(acc[fi][fj], a_l[fi], b_h[fj]);
                }
        }
    }

    // ---- epilogue ----
    const int lq = lane >> 2, lr = lane & 3;
    #pragma unroll
    for (int fi = 0; fi < 2; ++fi){
        #pragma unroll
        for (int fj = 0; fj < 8; ++fj){
            const float* cc = acc[fi][fj];
            const int lcol = wn*64 + fj*8 + lr*2;
            const int col0 = bx*128 + lcol;
            const int r0   = by*128 + wm*32 + fi*16 + lq;
            if (MODE == 1){
                float2 v0 = make_float2(cc[0] + bs[lcol], cc[1] + bs[lcol+1]);
                float2 v1 = make_float2(cc[2] + bs[lcol], cc[3] + bs[lcol+1]);
                *(float2*)&C[(size_t)r0*NC + col0]     = v0;
                *(float2*)&C[(size_t)(r0+8)*NC + col0] = v1;
            } else {
                #pragma unroll
                for (int h2 = 0; h2 < 2; ++h2){
                    const int m = r0 + 8*h2;
                    const int b = m >> 11, n = m & 2047;
                    #pragma unroll
                    for (int e = 0; e < 2; ++e){
                        const int ccol = col0 + e;
                        const float val = cc[2*h2 + e] + bs[lcol + e];
                        // qkv reshape (B,N,H,D,3): ccol = h*288 + d*3 + which
                        const int which = ccol % 3;
                        const int tt    = ccol / 3;
                        const int d     = tt % HDIM;
                        const int h     = tt / HDIM;
                        const int bh    = b*HEADS + h;
                        if (which == 2)
                            g_v[((size_t)bh*SEQ + n)*HDIM + d] = val;      // [bh][n][d]
                        else
                            ((which == 0) ? g_q : g_k)
                                [((size_t)bh*HDIM + d)*SEQ + n] = val;     // [bh][d][n]
                    }
                }
            }
        }
    }
}

// ============================================================================
// Flash attention (best measured config): fp32 online softmax, 256 threads,
// one block = (bh, 128-query tile), 8x8 micro-tile, f32x2 FMAs.
// softmax(S) applied, 1/sqrt(D) AFTER (faithful to reference).
// ============================================================================
__global__ void __launch_bounds__(256, 1) flash_kernel()
{
    extern __shared__ __align__(16) float smf[];
    float* Qs = smf;                 // [96][128]  k-major
    float* Ks = Qs + 96*128;         // [96][128]  k-major
    float* Vs = Ks + 96*128;         // [128][96]  n-major
    float* Ps = Vs + 128*96;         // [128][128] row-major

    const int tx = threadIdx.x, ty = threadIdx.y;
    const int tid = ty*16 + tx;
    const int n0 = blockIdx.x * 128;
    const int bh = blockIdx.y;

    const float* Qg = g_q + (size_t)bh*HDIM*SEQ;
    const float* Kg = g_k + (size_t)bh*HDIM*SEQ;
    const float* Vg = g_v + (size_t)bh*SEQ*HDIM;

    int row8[8];
    #pragma unroll
    for (int i = 0; i < 8; ++i) row8[i] = (i < 4) ? (4*ty + i) : (64 + 4*ty + i - 4);

    #pragma unroll
    for (int it = 0; it < 12; ++it){
        int f  = tid + it*256;
        int d  = f >> 5;
        int n4 = (f & 31) << 2;
        *(float4*)&Qs[d*128 + n4] = *(const float4*)&Qg[(size_t)d*SEQ + n0 + n4];
    }

    ull o2[8][3];
    float mx[8], l[8];
    #pragma unroll
    for (int i = 0; i < 8; ++i){
        mx[i] = -1e30f; l[i] = 0.f;
        o2[i][0] = 0ull; o2[i][1] = 0ull; o2[i][2] = 0ull;
    }

    #pragma unroll 1
    for (int t = 0; t < SEQ/128; ++t){
        __syncthreads();

        const int kn0 = t*128;
        #pragma unroll
        for (int it = 0; it < 12; ++it){
            int f  = tid + it*256;
            int d  = f >> 5;
            int n4 = (f & 31) << 2;
            *(float4*)&Ks[d*128 + n4] = *(const float4*)&Kg[(size_t)d*SEQ + kn0 + n4];
            int r  = f / 24;
            int d4 = (f % 24) << 2;
            *(float4*)&Vs[r*HDIM + d4] = *(const float4*)&Vg[(size_t)(kn0 + r)*HDIM + d4];
        }
        __syncthreads();

        ull s2[8][4];
        #pragma unroll
        for (int i = 0; i < 8; ++i)
            #pragma unroll
            for (int j = 0; j < 4; ++j) s2[i][j] = 0ull;

        #pragma unroll 4
        for (int k = 0; k < HDIM; ++k){
            float4 qa = *(float4*)&Qs[k*128 + 4*ty];
            float4 qb = *(float4*)&Qs[k*128 + 64 + 4*ty];
            ulonglong2 ka = *(const ulonglong2*)&Ks[k*128 + 4*tx];
            ulonglong2 kb = *(const ulonglong2*)&Ks[k*128 + 64 + 4*tx];
            float qv[8] = {qa.x, qa.y, qa.z, qa.w, qb.x, qb.y, qb.z, qb.w};
            #pragma unroll
            for (int i = 0; i < 8; ++i){
                ull qd = pack2(qv[i], qv[i]);
                s2[i][0] = fma2(qd, ka.x, s2[i][0]);
                s2[i][1] = fma2(qd, ka.y, s2[i][1]);
                s2[i][2] = fma2(qd, kb.x, s2[i][2]);
                s2[i][3] = fma2(qd, kb.y, s2[i][3]);
            }
        }

        #pragma unroll
        for (int i = 0; i < 8; ++i){
            float s[8];
            unpack2(s2[i][0], s[0], s[1]);
            unpack2(s2[i][1], s[2], s[3]);
            unpack2(s2[i][2], s[4], s[5]);
            unpack2(s2[i][3], s[6], s[7]);
            float tm = fmaxf(fmaxf(fmaxf(s[0], s[1]), fmaxf(s[2], s[3])),
                             fmaxf(fmaxf(s[4], s[5]), fmaxf(s[6], s[7])));
            #pragma unroll
            for (int off = 8; off > 0; off >>= 1)
                tm = fmaxf(tm, __shfl_xor_sync(0xffffffffu, tm, off, 16));
            const float mnew  = fmaxf(mx[i], tm);
            const float alpha = __expf(mx[i] - mnew);
            float p[8], rs = 0.f;
            #pragma unroll
            for (int u = 0; u < 8; ++u){ p[u] = __expf(s[u] - mnew); rs += p[u]; }
            #pragma unroll
            for (int off = 8; off > 0; off >>= 1)
                rs += __shfl_xor_sync(0xffffffffu, rs, off, 16);
            l[i] = l[i]*alpha + rs;
            mx[i] = mnew;
            const ull a2 = pack2(alpha, alpha);
            o2[i][0] = mul2(a2, o2[i][0]);
            o2[i][1] = mul2(a2, o2[i][1]);
            o2[i][2] = mul2(a2, o2[i][2]);
            *(float4*)&Ps[row8[i]*128 + 4*tx]      = make_float4(p[0], p[1], p[2], p[3]);
            *(float4*)&Ps[row8[i]*128 + 64 + 4*tx] = make_float4(p[4], p[5], p[6], p[7]);
        }
        __syncthreads();

        #pragma unroll 1
        for (int kk0 = 0; kk0 < 128; kk0 += 4){
            float4 pr[8];
            #pragma unroll
            for (int i = 0; i < 8; ++i)
                pr[i] = *(float4*)&Ps[row8[i]*128 + kk0];
            #pragma unroll
            for (int u = 0; u < 4; ++u){
                const int kk = kk0 + u;
                ull v0 = *(const ull*)&Vs[kk*HDIM + 2*tx];
                ull v1 = *(const ull*)&Vs[kk*HDIM + 2*tx + 32];
                ull v2 = *(const ull*)&Vs[kk*HDIM + 2*tx + 64];
                #pragma unroll
                for (int i = 0; i < 8; ++i){
                    const float pv = ((const float*)&pr[i])[u];
                    const ull pd = pack2(pv, pv);
                    o2[i][0] = fma2(pd, v0, o2[i][0]);
                    o2[i][1] = fma2(pd, v1, o2[i][1]);
                    o2[i][2] = fma2(pd, v2, o2[i][2]);
                }
            }
        }
    }

    const int b = bh / HEADS, h = bh % HEADS;
    #pragma unroll
    for (int i = 0; i < 8; ++i){
        const float sc = INV_SCALE / l[i];
        float* dst = g_attn + (size_t)(b*SEQ + n0 + row8[i])*EMB + h*HDIM;
        #pragma unroll
        for (int j = 0; j < 3; ++j){
            float lo, hi; unpack2(o2[i][j], lo, hi);
            dst[2*tx + 32*j + 0] = lo * sc;
            dst[2*tx + 32*j + 1] = hi * sc;
        }
    }
}

// ============================================================================
extern "C" void kernel_launch(void* const* d_in, const int* in_sizes, int n_in,
                              void* d_out, int out_size)
{
    const float* x      = (const float*)d_in[0];
    const float* w_qkv  = (const float*)d_in[1];
    const float* b_qkv  = (const float*)d_in[2];
    const float* w_proj = (const float*)d_in[3];
    const float* b_proj = (const float*)d_in[4];
    float* out = (float*)d_out;

    const int fl_smem = (96*128 + 96*128 + 128*96 + 128*128) * (int)sizeof(float); // 212992
    cudaFuncSetAttribute(flash_kernel, cudaFuncAttributeMaxDynamicSharedMemorySize, fl_smem);
    cudaFuncSetAttribute(gemm_mma<QKV_N, 0>, cudaFuncAttributeMaxDynamicSharedMemorySize, SG_SMEM);
    cudaFuncSetAttribute(gemm_mma<EMB, 1>,  cudaFuncAttributeMaxDynamicSharedMemorySize, SG_SMEM);

    // 1) QKV GEMM (mma.sync split-bf16) + bias + scatter
    gemm_mma<QKV_N, 0><<<dim3(QKV_N/128, ROWS/128), 256, SG_SMEM>>>(x, w_qkv, b_qkv, nullptr);
    // 2) flash attention (fp32 f32x2), 256 threads/block
    flash_kernel<<<dim3(SEQ/128, BATCH*HEADS), dim3(16, 16), fl_smem>>>();
    // 3) output projection (mma.sync split-bf16) + bias
    gemm_mma<EMB, 1><<<dim3(EMB/128, ROWS/128), 256, SG_SMEM>>>(nullptr, w_proj, b_proj, out);
}